// round 13
// baseline (speedup 1.0000x reference)
#include <cuda_runtime.h>
#include <cuda_bf16.h>
#include <cstdint>

#define FDIM 300
#define DIN  303
#define NLAST_MAX 100000
#define NCUR_MAX  50000
#define E_MAX     500000
#define BN_EPS    1e-5f

// K/N padded to 320 = 5 chunks of 64
#define KCHUNKS 5
#define NPAD    320
#define CHUNK_TILE_BYTES (NPAD * 64 * 2)   // 320 n-rows x 128B = 40960

// ---------------- static scratch (allocation-free rule) ----------------
__device__ float g_P[(size_t)NLAST_MAX * FDIM];   // 120 MB
__device__ float g_M[(size_t)NCUR_MAX * FDIM];    // 60 MB (raw seg-max)
__device__ int   g_counts[NCUR_MAX];
__device__ int   g_offs[NCUR_MAX + 1];
__device__ int   g_cursor[NCUR_MAX];
__device__ int   g_sortedLast[E_MAX];
__device__ float g_sum1[FDIM], g_sumsq1[FDIM], g_sum2[FDIM], g_sumsq2[FDIM];
__device__ float g_a1[FDIM], g_c1[FDIM];          // BN1 affine params
// B images: [half(hi/lo)][chunk][320 n x 64 k] bf16, PRE-SWIZZLED (granule ^= n&7)
__device__ __align__(16) char g_B1img[2 * KCHUNKS * CHUNK_TILE_BYTES];
__device__ __align__(16) char g_B2img[2 * KCHUNKS * CHUNK_TILE_BYTES];

// ---------------- init ----------------
__global__ void k_init(int nCur) {
    int i = blockIdx.x * blockDim.x + threadIdx.x;
    if (i < nCur) g_counts[i] = 0;
    if (i < FDIM) { g_sum1[i] = 0.f; g_sumsq1[i] = 0.f; g_sum2[i] = 0.f; g_sumsq2[i] = 0.f; }
}

// ---------------- counting sort of edges by cur_idx ----------------
__global__ void k_hist(const int* __restrict__ cur_idx, int E) {
    int i = blockIdx.x * blockDim.x + threadIdx.x;
    if (i < E) atomicAdd(&g_counts[cur_idx[i]], 1);
}

__global__ void k_scan(int n) {   // one block, 1024 threads
    __shared__ int sh[1024];
    int t = threadIdx.x;
    int carry = 0;
    for (int base = 0; base < n; base += 1024) {
        int x = (base + t < n) ? g_counts[base + t] : 0;
        sh[t] = x;
        __syncthreads();
        for (int off = 1; off < 1024; off <<= 1) {
            int y = (t >= off) ? sh[t - off] : 0;
            __syncthreads();
            sh[t] += y;
            __syncthreads();
        }
        int incl = sh[t];
        if (base + t < n) {
            int ex = carry + incl - x;
            g_offs[base + t]   = ex;
            g_cursor[base + t] = ex;
        }
        carry += sh[1023];
        __syncthreads();
    }
    if (t == 0) g_offs[n] = carry;
}

__global__ void k_scatter(const int* __restrict__ cur_idx,
                          const int* __restrict__ last_idx, int E) {
    int i = blockIdx.x * blockDim.x + threadIdx.x;
    if (i < E) {
        int c = cur_idx[i];
        int p = atomicAdd(&g_cursor[c], 1);
        g_sortedLast[p] = last_idx[i];
    }
}

// ---------------- build PRE-SWIZZLED bf16 hi/lo images of W1^T / W2^T ----------------
// B[n][kg] = W[kg][n]; within a row, 16B granule index g is stored at g^(n&7).
__global__ void k_convW(const float* __restrict__ W1, const float* __restrict__ W2) {
    int idx = blockIdx.x * blockDim.x + threadIdx.x;
    if (idx >= 2 * NPAD * NPAD) return;
    int which = idx / (NPAD * NPAD);
    int r = idx - which * (NPAD * NPAD);
    int kg = r / NPAD;   // global k
    int n  = r - kg * NPAD;
    float w = 0.f;
    if (which == 0) { if (kg < DIN  && n < FDIM) w = W1[(size_t)kg * FDIM + n]; }
    else            { if (kg < FDIM && n < FDIM) w = W2[(size_t)kg * FDIM + n]; }
    __nv_bfloat16 h = __float2bfloat16(w);
    __nv_bfloat16 l = __float2bfloat16(w - __bfloat162float(h));
    int chunk = kg >> 6, k = kg & 63;
    size_t off = (size_t)chunk * CHUNK_TILE_BYTES + (size_t)n * 128 +
                 (size_t)(((k >> 3) ^ (n & 7)) << 4) + (size_t)(k & 7) * 2;
    char* base = which ? g_B2img : g_B1img;
    *(__nv_bfloat16*)(base + off) = h;
    *(__nv_bfloat16*)(base + (size_t)KCHUNKS * CHUNK_TILE_BYTES + off) = l;
}

// ---------------- pipelined cp.async HMMA split-bf16 GEMM ----------------
// MODE 0: A = [feats|coors] (K=303), out = A@W1 + b1  -> g_P
// MODE 1: A = BN1affine(g_M) masked by seg count (K=300), out = ReLU(A@W2+b2) -> d_out
// CTA 128(M) x 160(N), 16 warps (4M x 4N), warp tile 32x40, K chunk 64, 2 stages.
// SMEM: rawA[2] (fp32) | bfA[2] (hi+lo) | B[2] (hi+lo), all XOR-granule swizzled.

#define RAWA_OFF 0            // 2 x 32768
#define BFA_OFF  65536        // 2 x 32768 (hi 16384 + lo 16384)
#define BB_OFF   131072       // 2 x 40960 (hi 20480 + lo 20480)
#define SMEM_TOT 212992

__device__ __forceinline__ void cp16(uint32_t dst, const void* src, int srcbytes) {
    asm volatile("cp.async.cg.shared.global [%0], [%1], 16, %2;"
                 :: "r"(dst), "l"(src), "r"(srcbytes));
}
#define CP_COMMIT() asm volatile("cp.async.commit_group;")
#define CP_WAIT1()  asm volatile("cp.async.wait_group 1;")
#define CP_WAIT0()  asm volatile("cp.async.wait_group 0;")

__device__ __forceinline__ void mma_bf16(float* d, const uint32_t* a,
                                         uint32_t b0, uint32_t b1) {
    asm volatile("mma.sync.aligned.m16n8k16.row.col.f32.bf16.bf16.f32 "
                 "{%0,%1,%2,%3}, {%4,%5,%6,%7}, {%8,%9}, {%0,%1,%2,%3};"
                 : "+f"(d[0]), "+f"(d[1]), "+f"(d[2]), "+f"(d[3])
                 : "r"(a[0]), "r"(a[1]), "r"(a[2]), "r"(a[3]), "r"(b0), "r"(b1));
}

__device__ __forceinline__ void split2(float x, float y, uint32_t& h, uint32_t& l) {
    __nv_bfloat162 hb, lb;
    hb.x = __float2bfloat16(x); hb.y = __float2bfloat16(y);
    lb.x = __float2bfloat16(x - __bfloat162float(hb.x));
    lb.y = __float2bfloat16(y - __bfloat162float(hb.y));
    h = *reinterpret_cast<uint32_t*>(&hb);
    l = *reinterpret_cast<uint32_t*>(&lb);
}

template<int MODE>
__global__ __launch_bounds__(512)
void k_gemm_mma(const float* __restrict__ feats, const float* __restrict__ coors,
                const float* __restrict__ bias, float* __restrict__ outp, int Mrows) {
    extern __shared__ char smem[];
    __shared__ float sA[NPAD], sC[NPAD];
    uint32_t sb = (uint32_t)__cvta_generic_to_shared(smem);
    int t = threadIdx.x;
    int warp = t >> 5, lane = t & 31;
    int g = lane >> 2, tg = lane & 3;
    int wm = warp & 3, wn = warp >> 2;          // 4 x 4 warp grid
    int mBase = blockIdx.x * 128;
    int nBase = blockIdx.y * 160;

    const float* Ain = (MODE == 0) ? feats : (const float*)g_M;
    float*       Opt = (MODE == 0) ? (float*)g_P : outp;
    const char* Bimg = MODE ? g_B2img : g_B1img;

    if (MODE == 1) {
        for (int i = t; i < NPAD; i += 512) {
            sA[i] = (i < FDIM) ? g_a1[i] : 0.f;
            sC[i] = (i < FDIM) ? g_c1[i] : 0.f;
        }
    }

    float acc[2][5][4];
#pragma unroll
    for (int mf = 0; mf < 2; mf++)
#pragma unroll
        for (int nf = 0; nf < 5; nf++)
#pragma unroll
            for (int c = 0; c < 4; c++) acc[mf][nf][c] = 0.f;

    // ---- copy issue (chunk c) ----
    auto issue_copy = [&](int c) {
        int s = c & 1;
        // A: 128 rows x 16 fp32-granules = 2048
#pragma unroll
        for (int it = 0; it < 4; it++) {
            int id = it * 512 + t;
            int r = id >> 4, g32 = id & 15;
            int gm = mBase + r;
            int k  = c * 64 + g32 * 4;
            bool valid = (gm < Mrows && k < FDIM);
            const float* src = valid ? (Ain + (size_t)gm * FDIM + k) : Ain;
            uint32_t dst = sb + RAWA_OFF + s * 32768 + r * 256 + ((g32 ^ (r & 15)) << 4);
            cp16(dst, src, valid ? 16 : 0);
        }
        // B: 160 rows x 8 granules x 2 halves = 2560, image pre-swizzled
#pragma unroll
        for (int it = 0; it < 5; it++) {
            int id = it * 512 + t;
            int h = (id >= 1280) ? 1 : 0;
            int j = id - h * 1280;
            int n = j >> 3, gq = j & 7;
            const char* src = Bimg + (size_t)h * (KCHUNKS * CHUNK_TILE_BYTES)
                            + (size_t)c * CHUNK_TILE_BYTES
                            + (size_t)(nBase + n) * 128 + gq * 16;
            uint32_t dst = sb + BB_OFF + s * 40960 + h * 20480 + n * 128 + gq * 16;
            cp16(dst, src, 16);
        }
    };

    // ---- convert rawA(c) -> bfA(c) hi/lo (+ BN1 affine / coor patch) ----
    auto convert = [&](int c) {
        int s = c & 1;
        const char* raw = smem + RAWA_OFF + s * 32768;
        char* dh = smem + BFA_OFF + s * 32768;
        char* dl = dh + 16384;
#pragma unroll
        for (int it = 0; it < 2; it++) {
            int ob = it * 512 + t;            // 1024 units (128 rows x 8 granule-pairs)
            int r = ob >> 3, gb = ob & 7;
            int gm = mBase + r;
            const float4* rp = (const float4*)(raw + r * 256);
            float4 q0 = rp[(2 * gb) ^ (r & 15)];
            float4 q1 = rp[(2 * gb + 1) ^ (r & 15)];
            if (MODE == 0) {
                if (c == 4 && gb == 5 && gm < Mrows) {
                    q1.x = coors[gm * 3 + 0];
                    q1.y = coors[gm * 3 + 1];
                    q1.z = coors[gm * 3 + 2];
                    q1.w = 0.f;
                }
            } else {
                bool nz = (gm < Mrows) && (g_offs[gm + 1] > g_offs[gm]);
                if (nz) {
                    int k = c * 64 + gb * 8;
                    q0.x = fmaf(sA[k + 0], q0.x, sC[k + 0]);
                    q0.y = fmaf(sA[k + 1], q0.y, sC[k + 1]);
                    q0.z = fmaf(sA[k + 2], q0.z, sC[k + 2]);
                    q0.w = fmaf(sA[k + 3], q0.w, sC[k + 3]);
                    q1.x = fmaf(sA[k + 4], q1.x, sC[k + 4]);
                    q1.y = fmaf(sA[k + 5], q1.y, sC[k + 5]);
                    q1.z = fmaf(sA[k + 6], q1.z, sC[k + 6]);
                    q1.w = fmaf(sA[k + 7], q1.w, sC[k + 7]);
                } else {
                    q0 = make_float4(0.f, 0.f, 0.f, 0.f);
                    q1 = make_float4(0.f, 0.f, 0.f, 0.f);
                }
            }
            uint4 hv, lv;
            split2(q0.x, q0.y, hv.x, lv.x);
            split2(q0.z, q0.w, hv.y, lv.y);
            split2(q1.x, q1.y, hv.z, lv.z);
            split2(q1.z, q1.w, hv.w, lv.w);
            int doff = r * 128 + (((gb) ^ (r & 7)) << 4);
            *(uint4*)(dh + doff) = hv;
            *(uint4*)(dl + doff) = lv;
        }
    };

    // ---- MMA over one chunk in stage s ----
    auto mma_chunk = [&](int s) {
        const char* Ah = smem + BFA_OFF + s * 32768;
        const char* Al = Ah + 16384;
        const char* Bh = smem + BB_OFF + s * 40960;
        const char* Bl = Bh + 20480;
#pragma unroll
        for (int ks = 0; ks < 4; ks++) {
            uint32_t ah[2][4], al[2][4];
#pragma unroll
            for (int mf = 0; mf < 2; mf++) {
                int r0 = wm * 32 + mf * 16 + g;
                int r1 = r0 + 8;
                int a00 = r0 * 128 + (((2 * ks)     ^ (r0 & 7)) << 4) + 4 * tg;
                int a01 = r0 * 128 + (((2 * ks + 1) ^ (r0 & 7)) << 4) + 4 * tg;
                int a10 = r1 * 128 + (((2 * ks)     ^ (r1 & 7)) << 4) + 4 * tg;
                int a11 = r1 * 128 + (((2 * ks + 1) ^ (r1 & 7)) << 4) + 4 * tg;
                ah[mf][0] = *(const uint32_t*)(Ah + a00);
                ah[mf][1] = *(const uint32_t*)(Ah + a10);
                ah[mf][2] = *(const uint32_t*)(Ah + a01);
                ah[mf][3] = *(const uint32_t*)(Ah + a11);
                al[mf][0] = *(const uint32_t*)(Al + a00);
                al[mf][1] = *(const uint32_t*)(Al + a10);
                al[mf][2] = *(const uint32_t*)(Al + a01);
                al[mf][3] = *(const uint32_t*)(Al + a11);
            }
#pragma unroll
            for (int nf = 0; nf < 5; nf++) {
                int nr = wn * 40 + nf * 8 + g;
                int b0 = nr * 128 + (((2 * ks)     ^ (nr & 7)) << 4) + 4 * tg;
                int b1 = nr * 128 + (((2 * ks + 1) ^ (nr & 7)) << 4) + 4 * tg;
                uint32_t bh0 = *(const uint32_t*)(Bh + b0);
                uint32_t bh1 = *(const uint32_t*)(Bh + b1);
                uint32_t bl0 = *(const uint32_t*)(Bl + b0);
                uint32_t bl1 = *(const uint32_t*)(Bl + b1);
#pragma unroll
                for (int mf = 0; mf < 2; mf++) {
                    mma_bf16(acc[mf][nf], ah[mf], bh0, bh1);
                    mma_bf16(acc[mf][nf], ah[mf], bl0, bl1);
                    mma_bf16(acc[mf][nf], al[mf], bh0, bh1);
                }
            }
        }
    };

    // ---- software pipeline ----
    issue_copy(0); CP_COMMIT();
    issue_copy(1); CP_COMMIT();
    CP_WAIT1();
    __syncthreads();
    convert(0);
    __syncthreads();

#pragma unroll
    for (int i = 0; i < KCHUNKS; i++) {
        mma_chunk(i & 1);
        __syncthreads();
        if (i + 2 < KCHUNKS) { issue_copy(i + 2); CP_COMMIT(); }
        if (i + 1 < KCHUNKS) {
            if (i + 2 < KCHUNKS) { CP_WAIT1(); } else { CP_WAIT0(); }
            __syncthreads();
            convert(i + 1);
            __syncthreads();
        }
    }

    // ---- epilogue: bias (+ReLU for MODE1), store fp32 pairs ----
#pragma unroll
    for (int mf = 0; mf < 2; mf++) {
#pragma unroll
        for (int nf = 0; nf < 5; nf++) {
            int col = nBase + wn * 40 + nf * 8 + 2 * tg;
            if (col >= FDIM) continue;
            float bx = bias[col], by = bias[col + 1];
            int r0 = mBase + wm * 32 + mf * 16 + g;
#pragma unroll
            for (int h = 0; h < 2; h++) {
                int row = r0 + h * 8;
                if (row < Mrows) {
                    float vx = acc[mf][nf][h * 2 + 0] + bx;
                    float vy = acc[mf][nf][h * 2 + 1] + by;
                    if (MODE == 1) { vx = fmaxf(vx, 0.f); vy = fmaxf(vy, 0.f); }
                    *reinterpret_cast<float2*>(Opt + (size_t)row * FDIM + col) =
                        make_float2(vx, vy);
                }
            }
        }
    }
}

// ---------------- edge pass: seg-max of r=ReLU(P[l]-Q[c]) + BN1 stats ----------------
// Q computed on the fly: Q[c][n] = sum_j coors[c][j] * W1[300+j][n]
#define SEGS 32
__global__ __launch_bounds__(128)
void k_edge(const float* __restrict__ cur_coors, const float* __restrict__ W1, int nCur) {
    __shared__ float sW[3 * FDIM];
    int t = threadIdx.x;
    for (int i = t; i < 3 * FDIM; i += 128) {
        int r = i / FDIM, n = i - r * FDIM;
        sW[i] = W1[(size_t)(FDIM + r) * FDIM + n];
    }
    __syncthreads();

    int segBase = blockIdx.x * SEGS;
    bool v2 = (256 + t) < FDIM;

    float s0 = 0.f, s1 = 0.f, s2 = 0.f;
    float q0sq = 0.f, q1sq = 0.f, q2sq = 0.f;

    for (int si = 0; si < SEGS; si++) {
        int c = segBase + si;
        if (c >= nCur) break;
        int e0 = g_offs[c];
        int e1 = g_offs[c + 1];
        if (e0 == e1) continue;

        float x0 = cur_coors[c * 3 + 0];
        float x1 = cur_coors[c * 3 + 1];
        float x2 = cur_coors[c * 3 + 2];
        float q0 = x0 * sW[t]       + x1 * sW[FDIM + t]       + x2 * sW[2 * FDIM + t];
        float q1 = x0 * sW[128 + t] + x1 * sW[FDIM + 128 + t] + x2 * sW[2 * FDIM + 128 + t];
        float q2 = v2 ? (x0 * sW[256 + t] + x1 * sW[FDIM + 256 + t] + x2 * sW[2 * FDIM + 256 + t]) : 0.f;

        size_t mb = (size_t)c * FDIM;
        float m0 = 0.f, m1 = 0.f, m2 = 0.f;
        for (int e = e0; e < e1; e++) {
            int l = g_sortedLast[e];
            const float* Pr = g_P + (size_t)l * FDIM;
            float r0 = fmaxf(Pr[t] - q0, 0.f);
            float r1 = fmaxf(Pr[128 + t] - q1, 0.f);
            float r2 = v2 ? fmaxf(Pr[256 + t] - q2, 0.f) : 0.f;
            m0 = fmaxf(m0, r0); s0 += r0; q0sq += r0 * r0;
            m1 = fmaxf(m1, r1); s1 += r1; q1sq += r1 * r1;
            m2 = fmaxf(m2, r2); s2 += r2; q2sq += r2 * r2;
        }
        g_M[mb + t]       = m0;
        g_M[mb + 128 + t] = m1;
        if (v2) g_M[mb + 256 + t] = m2;
    }

    atomicAdd(&g_sum1[t], s0);         atomicAdd(&g_sumsq1[t], q0sq);
    atomicAdd(&g_sum1[128 + t], s1);   atomicAdd(&g_sumsq1[128 + t], q1sq);
    if (v2) { atomicAdd(&g_sum1[256 + t], s2); atomicAdd(&g_sumsq1[256 + t], q2sq); }
}

// ---------------- BN1 affine params from edge-pass stats ----------------
__global__ void k_bnparam(const float* __restrict__ g1, const float* __restrict__ be1, int E) {
    int n = blockIdx.x * blockDim.x + threadIdx.x;
    if (n >= FDIM) return;
    float invE = 1.f / (float)E;
    float mean = g_sum1[n] * invE;
    float var  = fmaxf(g_sumsq1[n] * invE - mean * mean, 0.f);
    float a = g1[n] * rsqrtf(var + BN_EPS);
    g_a1[n] = a;
    g_c1[n] = be1[n] - mean * a;
}

// ---------------- BN2 stats over out ----------------
__global__ __launch_bounds__(320)
void k_stats2(const float* __restrict__ out, int nCur) {
    int c = threadIdx.x;
    if (c >= FDIM) return;
    int r0 = blockIdx.x * 128;
    int r1 = r0 + 128; if (r1 > nCur) r1 = nCur;
    float s = 0.f, q = 0.f;
    for (int r = r0; r < r1; r++) {
        float v = out[(size_t)r * FDIM + c];
        s += v; q += v * v;
    }
    atomicAdd(&g_sum2[c], s);
    atomicAdd(&g_sumsq2[c], q);
}

// ---------------- final BN2 over d_out (in place) ----------------
__global__ void k_bn2(const float* __restrict__ g2, const float* __restrict__ be2,
                      float* __restrict__ out, int nCur) {
    int idx = blockIdx.x * blockDim.x + threadIdx.x;
    if (idx >= nCur * FDIM) return;
    int n = idx % FDIM;
    float invN = 1.f / (float)nCur;
    float mean = g_sum2[n] * invN;
    float var  = fmaxf(g_sumsq2[n] * invN - mean * mean, 0.f);
    float a = g2[n] * rsqrtf(var + BN_EPS);
    float b = be2[n] - mean * a;
    out[idx] = fmaf(a, out[idx], b);
}

// ---------------- launch ----------------
extern "C" void kernel_launch(void* const* d_in, const int* in_sizes, int n_in,
                              void* d_out, int out_size) {
    const float* last_coors    = (const float*)d_in[0];
    const float* last_features = (const float*)d_in[1];
    const float* current_coors = (const float*)d_in[2];
    const int*   cur_idx       = (const int*)d_in[3];
    const int*   last_idx      = (const int*)d_in[4];
    const float* W1            = (const float*)d_in[5];
    const float* b1            = (const float*)d_in[6];
    const float* g1            = (const float*)d_in[7];
    const float* be1           = (const float*)d_in[8];
    const float* W2            = (const float*)d_in[9];
    const float* b2            = (const float*)d_in[10];
    const float* g2            = (const float*)d_in[11];
    const float* be2           = (const float*)d_in[12];
    float* out = (float*)d_out;

    int nLast = in_sizes[0] / 3;
    int nCur  = in_sizes[2] / 3;
    int E     = in_sizes[3];

    cudaFuncSetAttribute(k_gemm_mma<0>, cudaFuncAttributeMaxDynamicSharedMemorySize, SMEM_TOT);
    cudaFuncSetAttribute(k_gemm_mma<1>, cudaFuncAttributeMaxDynamicSharedMemorySize, SMEM_TOT);

    // Launch order places k_gemm_mma<0> in the ncu capture slot (4th launch).
    // 1: W images (needed by gemm1)
    k_convW<<<(2 * NPAD * NPAD + 255) / 256, 256>>>(W1, W2);
    // 2: init counters/stats
    {
        int n = nCur > FDIM ? nCur : FDIM;
        k_init<<<(n + 255) / 256, 256>>>(nCur);
    }
    // 3: histogram
    k_hist<<<(E + 255) / 256, 256>>>(cur_idx, E);
    // 4: GEMM1 (profiled slot): P = [feats|coors] @ W1 + b1 -> g_P
    {
        dim3 grid((nLast + 127) / 128, 2);
        k_gemm_mma<0><<<grid, 512, SMEM_TOT>>>(last_features, last_coors, b1, nullptr, nLast);
    }
    // 5-6: finish counting sort
    k_scan<<<1, 1024>>>(nCur);
    k_scatter<<<(E + 255) / 256, 256>>>(cur_idx, last_idx, E);
    // 7: edge pass (fused Q): seg-max + BN1 stats -> g_M, g_sum1/g_sumsq1
    k_edge<<<(nCur + SEGS - 1) / SEGS, 128>>>(current_coors, W1, nCur);
    // 8: BN1 affine params
    k_bnparam<<<(FDIM + 127) / 128, 128>>>(g1, be1, E);
    // 9: GEMM2 (BN1 affine fused into A-fill): out = ReLU(BN1(g_M) @ W2 + b2)
    {
        dim3 grid((nCur + 127) / 128, 2);
        k_gemm_mma<1><<<grid, 512, SMEM_TOT>>>(nullptr, nullptr, b2, out, nCur);
    }
    // 10-11: BN2 stats + final affine
    k_stats2<<<(nCur + 127) / 128, 320>>>(out, nCur);
    k_bn2<<<(nCur * FDIM + 255) / 256, 256>>>(g2, be2, out, nCur);
}

// round 15
// speedup vs baseline: 1.1453x; 1.1453x over previous
#include <cuda_runtime.h>
#include <cuda_bf16.h>
#include <cstdint>

#define FDIM 300
#define DIN  303
#define NLAST_MAX 100000
#define NCUR_MAX  50000
#define E_MAX     500000
#define BN_EPS    1e-5f

// K/N padded to 320 = 5 chunks of 64
#define KCHUNKS 5
#define NPAD    320
#define CHUNK_TILE_BYTES (NPAD * 64 * 2)   // 320 n-rows x 128B = 40960

// ---------------- static scratch (allocation-free rule) ----------------
__device__ float g_P[(size_t)NLAST_MAX * FDIM];   // 120 MB
__device__ float g_M[(size_t)NCUR_MAX * FDIM];    // 60 MB (raw seg-max)
__device__ int   g_counts[NCUR_MAX];
__device__ int   g_offs[NCUR_MAX + 1];
__device__ int   g_cursor[NCUR_MAX];
__device__ int   g_sortedLast[E_MAX];
__device__ int   g_bsums[64], g_bpre[64];
__device__ float g_sum1[FDIM], g_sumsq1[FDIM], g_sum2[FDIM], g_sumsq2[FDIM];
__device__ float g_a1[FDIM], g_c1[FDIM];          // BN1 affine params
// B images: [half(hi/lo)][chunk][320 n x 64 k] bf16, PRE-SWIZZLED (granule ^= n&7)
__device__ __align__(16) char g_B1img[2 * KCHUNKS * CHUNK_TILE_BYTES];
__device__ __align__(16) char g_B2img[2 * KCHUNKS * CHUNK_TILE_BYTES];

// ---------------- init ----------------
__global__ void k_init(int nCur) {
    int i = blockIdx.x * blockDim.x + threadIdx.x;
    if (i < nCur) g_counts[i] = 0;
    if (i < FDIM) { g_sum1[i] = 0.f; g_sumsq1[i] = 0.f; g_sum2[i] = 0.f; g_sumsq2[i] = 0.f; }
}

// ---------------- counting sort of edges by cur_idx ----------------
__global__ void k_hist(const int* __restrict__ cur_idx, int E) {
    int i = blockIdx.x * blockDim.x + threadIdx.x;
    if (i < E) atomicAdd(&g_counts[cur_idx[i]], 1);
}

// ---- parallel scan, phase A: per-block (1024-wide) local exclusive scan ----
__global__ __launch_bounds__(1024)
void k_scanA(int n) {
    __shared__ int sh[1024];
    int t = threadIdx.x;
    int i = blockIdx.x * 1024 + t;
    int x = (i < n) ? g_counts[i] : 0;
    sh[t] = x;
    __syncthreads();
    for (int off = 1; off < 1024; off <<= 1) {
        int y = (t >= off) ? sh[t - off] : 0;
        __syncthreads();
        sh[t] += y;
        __syncthreads();
    }
    if (i < n) g_offs[i] = sh[t] - x;          // local exclusive
    if (t == 1023) g_bsums[blockIdx.x] = sh[1023];
}

// ---- phase B: exclusive scan of block sums (tiny, serial) ----
__global__ void k_scanB(int n, int nb) {
    if (threadIdx.x == 0) {
        int acc = 0;
        for (int b = 0; b < nb; b++) {
            g_bpre[b] = acc;
            acc += g_bsums[b];
        }
        g_offs[n] = acc;
    }
}

// ---- phase C: add block prefix, materialize cursor ----
__global__ void k_scanC(int n) {
    int i = blockIdx.x * blockDim.x + threadIdx.x;
    if (i < n) {
        int v = g_offs[i] + g_bpre[i >> 10];
        g_offs[i]   = v;
        g_cursor[i] = v;
    }
}

__global__ void k_scatter(const int* __restrict__ cur_idx,
                          const int* __restrict__ last_idx, int E) {
    int i = blockIdx.x * blockDim.x + threadIdx.x;
    if (i < E) {
        int c = cur_idx[i];
        int p = atomicAdd(&g_cursor[c], 1);
        g_sortedLast[p] = last_idx[i];
    }
}

// ---------------- build PRE-SWIZZLED bf16 hi/lo images of W1^T / W2^T ----------------
// B[n][kg] = W[kg][n]; within a row, 16B granule index g is stored at g^(n&7).
__global__ void k_convW(const float* __restrict__ W1, const float* __restrict__ W2) {
    int idx = blockIdx.x * blockDim.x + threadIdx.x;
    if (idx >= 2 * NPAD * NPAD) return;
    int which = idx / (NPAD * NPAD);
    int r = idx - which * (NPAD * NPAD);
    int kg = r / NPAD;   // global k
    int n  = r - kg * NPAD;
    float w = 0.f;
    if (which == 0) { if (kg < DIN  && n < FDIM) w = W1[(size_t)kg * FDIM + n]; }
    else            { if (kg < FDIM && n < FDIM) w = W2[(size_t)kg * FDIM + n]; }
    __nv_bfloat16 h = __float2bfloat16(w);
    __nv_bfloat16 l = __float2bfloat16(w - __bfloat162float(h));
    int chunk = kg >> 6, k = kg & 63;
    size_t off = (size_t)chunk * CHUNK_TILE_BYTES + (size_t)n * 128 +
                 (size_t)(((k >> 3) ^ (n & 7)) << 4) + (size_t)(k & 7) * 2;
    char* base = which ? g_B2img : g_B1img;
    *(__nv_bfloat16*)(base + off) = h;
    *(__nv_bfloat16*)(base + (size_t)KCHUNKS * CHUNK_TILE_BYTES + off) = l;
}

// ---------------- pipelined cp.async HMMA split-bf16 GEMM ----------------
// MODE 0: A = [feats|coors] (K=303), out = A@W1 + b1  -> g_P
// MODE 1: A = BN1affine(g_M) masked by seg count (K=300), out = ReLU(A@W2+b2) -> d_out
// CTA 128(M) x 160(N), 16 warps (4M x 4N), warp tile 32x40, K chunk 64, 2 stages.

#define RAWA_OFF 0            // 2 x 32768
#define BFA_OFF  65536        // 2 x 32768 (hi 16384 + lo 16384)
#define BB_OFF   131072       // 2 x 40960 (hi 20480 + lo 20480)
#define SMEM_TOT 212992

__device__ __forceinline__ void cp16(uint32_t dst, const void* src, int srcbytes) {
    asm volatile("cp.async.cg.shared.global [%0], [%1], 16, %2;"
                 :: "r"(dst), "l"(src), "r"(srcbytes));
}
#define CP_COMMIT() asm volatile("cp.async.commit_group;")
#define CP_WAIT1()  asm volatile("cp.async.wait_group 1;")
#define CP_WAIT0()  asm volatile("cp.async.wait_group 0;")

__device__ __forceinline__ void mma_bf16(float* d, const uint32_t* a,
                                         uint32_t b0, uint32_t b1) {
    asm volatile("mma.sync.aligned.m16n8k16.row.col.f32.bf16.bf16.f32 "
                 "{%0,%1,%2,%3}, {%4,%5,%6,%7}, {%8,%9}, {%0,%1,%2,%3};"
                 : "+f"(d[0]), "+f"(d[1]), "+f"(d[2]), "+f"(d[3])
                 : "r"(a[0]), "r"(a[1]), "r"(a[2]), "r"(a[3]), "r"(b0), "r"(b1));
}

__device__ __forceinline__ void split2(float x, float y, uint32_t& h, uint32_t& l) {
    __nv_bfloat162 hb, lb;
    hb.x = __float2bfloat16(x); hb.y = __float2bfloat16(y);
    lb.x = __float2bfloat16(x - __bfloat162float(hb.x));
    lb.y = __float2bfloat16(y - __bfloat162float(hb.y));
    h = *reinterpret_cast<uint32_t*>(&hb);
    l = *reinterpret_cast<uint32_t*>(&lb);
}

template<int MODE>
__global__ __launch_bounds__(512)
void k_gemm_mma(const float* __restrict__ feats, const float* __restrict__ coors,
                const float* __restrict__ bias, float* __restrict__ outp, int Mrows) {
    extern __shared__ char smem[];
    __shared__ float sA[NPAD], sC[NPAD];
    uint32_t sb = (uint32_t)__cvta_generic_to_shared(smem);
    int t = threadIdx.x;
    int warp = t >> 5, lane = t & 31;
    int g = lane >> 2, tg = lane & 3;
    int wm = warp & 3, wn = warp >> 2;          // 4 x 4 warp grid
    int mBase = blockIdx.x * 128;
    int nBase = blockIdx.y * 160;

    const float* Ain = (MODE == 0) ? feats : (const float*)g_M;
    float*       Opt = (MODE == 0) ? (float*)g_P : outp;
    const char* Bimg = MODE ? g_B2img : g_B1img;

    if (MODE == 1) {
        for (int i = t; i < NPAD; i += 512) {
            sA[i] = (i < FDIM) ? g_a1[i] : 0.f;
            sC[i] = (i < FDIM) ? g_c1[i] : 0.f;
        }
    }

    float acc[2][5][4];
#pragma unroll
    for (int mf = 0; mf < 2; mf++)
#pragma unroll
        for (int nf = 0; nf < 5; nf++)
#pragma unroll
            for (int c = 0; c < 4; c++) acc[mf][nf][c] = 0.f;

    auto issue_copy = [&](int c) {
        int s = c & 1;
#pragma unroll
        for (int it = 0; it < 4; it++) {
            int id = it * 512 + t;
            int r = id >> 4, g32 = id & 15;
            int gm = mBase + r;
            int k  = c * 64 + g32 * 4;
            bool valid = (gm < Mrows && k < FDIM);
            const float* src = valid ? (Ain + (size_t)gm * FDIM + k) : Ain;
            uint32_t dst = sb + RAWA_OFF + s * 32768 + r * 256 + ((g32 ^ (r & 15)) << 4);
            cp16(dst, src, valid ? 16 : 0);
        }
#pragma unroll
        for (int it = 0; it < 5; it++) {
            int id = it * 512 + t;
            int h = (id >= 1280) ? 1 : 0;
            int j = id - h * 1280;
            int n = j >> 3, gq = j & 7;
            const char* src = Bimg + (size_t)h * (KCHUNKS * CHUNK_TILE_BYTES)
                            + (size_t)c * CHUNK_TILE_BYTES
                            + (size_t)(nBase + n) * 128 + gq * 16;
            uint32_t dst = sb + BB_OFF + s * 40960 + h * 20480 + n * 128 + gq * 16;
            cp16(dst, src, 16);
        }
    };

    auto convert = [&](int c) {
        int s = c & 1;
        const char* raw = smem + RAWA_OFF + s * 32768;
        char* dh = smem + BFA_OFF + s * 32768;
        char* dl = dh + 16384;
#pragma unroll
        for (int it = 0; it < 2; it++) {
            int ob = it * 512 + t;
            int r = ob >> 3, gb = ob & 7;
            int gm = mBase + r;
            const float4* rp = (const float4*)(raw + r * 256);
            float4 q0 = rp[(2 * gb) ^ (r & 15)];
            float4 q1 = rp[(2 * gb + 1) ^ (r & 15)];
            if (MODE == 0) {
                if (c == 4 && gb == 5 && gm < Mrows) {
                    q1.x = coors[gm * 3 + 0];
                    q1.y = coors[gm * 3 + 1];
                    q1.z = coors[gm * 3 + 2];
                    q1.w = 0.f;
                }
            } else {
                bool nz = (gm < Mrows) && (g_offs[gm + 1] > g_offs[gm]);
                if (nz) {
                    int k = c * 64 + gb * 8;
                    q0.x = fmaf(sA[k + 0], q0.x, sC[k + 0]);
                    q0.y = fmaf(sA[k + 1], q0.y, sC[k + 1]);
                    q0.z = fmaf(sA[k + 2], q0.z, sC[k + 2]);
                    q0.w = fmaf(sA[k + 3], q0.w, sC[k + 3]);
                    q1.x = fmaf(sA[k + 4], q1.x, sC[k + 4]);
                    q1.y = fmaf(sA[k + 5], q1.y, sC[k + 5]);
                    q1.z = fmaf(sA[k + 6], q1.z, sC[k + 6]);
                    q1.w = fmaf(sA[k + 7], q1.w, sC[k + 7]);
                } else {
                    q0 = make_float4(0.f, 0.f, 0.f, 0.f);
                    q1 = make_float4(0.f, 0.f, 0.f, 0.f);
                }
            }
            uint4 hv, lv;
            split2(q0.x, q0.y, hv.x, lv.x);
            split2(q0.z, q0.w, hv.y, lv.y);
            split2(q1.x, q1.y, hv.z, lv.z);
            split2(q1.z, q1.w, hv.w, lv.w);
            int doff = r * 128 + (((gb) ^ (r & 7)) << 4);
            *(uint4*)(dh + doff) = hv;
            *(uint4*)(dl + doff) = lv;
        }
    };

    auto mma_chunk = [&](int s) {
        const char* Ah = smem + BFA_OFF + s * 32768;
        const char* Al = Ah + 16384;
        const char* Bh = smem + BB_OFF + s * 40960;
        const char* Bl = Bh + 20480;
#pragma unroll
        for (int ks = 0; ks < 4; ks++) {
            uint32_t ah[2][4], al[2][4];
#pragma unroll
            for (int mf = 0; mf < 2; mf++) {
                int r0 = wm * 32 + mf * 16 + g;
                int r1 = r0 + 8;
                int a00 = r0 * 128 + (((2 * ks)     ^ (r0 & 7)) << 4) + 4 * tg;
                int a01 = r0 * 128 + (((2 * ks + 1) ^ (r0 & 7)) << 4) + 4 * tg;
                int a10 = r1 * 128 + (((2 * ks)     ^ (r1 & 7)) << 4) + 4 * tg;
                int a11 = r1 * 128 + (((2 * ks + 1) ^ (r1 & 7)) << 4) + 4 * tg;
                ah[mf][0] = *(const uint32_t*)(Ah + a00);
                ah[mf][1] = *(const uint32_t*)(Ah + a10);
                ah[mf][2] = *(const uint32_t*)(Ah + a01);
                ah[mf][3] = *(const uint32_t*)(Ah + a11);
                al[mf][0] = *(const uint32_t*)(Al + a00);
                al[mf][1] = *(const uint32_t*)(Al + a10);
                al[mf][2] = *(const uint32_t*)(Al + a01);
                al[mf][3] = *(const uint32_t*)(Al + a11);
            }
#pragma unroll
            for (int nf = 0; nf < 5; nf++) {
                int nr = wn * 40 + nf * 8 + g;
                int b0 = nr * 128 + (((2 * ks)     ^ (nr & 7)) << 4) + 4 * tg;
                int b1 = nr * 128 + (((2 * ks + 1) ^ (nr & 7)) << 4) + 4 * tg;
                uint32_t bh0 = *(const uint32_t*)(Bh + b0);
                uint32_t bh1 = *(const uint32_t*)(Bh + b1);
                uint32_t bl0 = *(const uint32_t*)(Bl + b0);
                uint32_t bl1 = *(const uint32_t*)(Bl + b1);
#pragma unroll
                for (int mf = 0; mf < 2; mf++) {
                    mma_bf16(acc[mf][nf], ah[mf], bh0, bh1);
                    mma_bf16(acc[mf][nf], ah[mf], bl0, bl1);
                    mma_bf16(acc[mf][nf], al[mf], bh0, bh1);
                }
            }
        }
    };

    issue_copy(0); CP_COMMIT();
    issue_copy(1); CP_COMMIT();
    CP_WAIT1();
    __syncthreads();
    convert(0);
    __syncthreads();

#pragma unroll
    for (int i = 0; i < KCHUNKS; i++) {
        mma_chunk(i & 1);
        __syncthreads();
        if (i + 2 < KCHUNKS) { issue_copy(i + 2); CP_COMMIT(); }
        if (i + 1 < KCHUNKS) {
            if (i + 2 < KCHUNKS) { CP_WAIT1(); } else { CP_WAIT0(); }
            __syncthreads();
            convert(i + 1);
            __syncthreads();
        }
    }

#pragma unroll
    for (int mf = 0; mf < 2; mf++) {
#pragma unroll
        for (int nf = 0; nf < 5; nf++) {
            int col = nBase + wn * 40 + nf * 8 + 2 * tg;
            if (col >= FDIM) continue;
            float bx = bias[col], by = bias[col + 1];
            int r0 = mBase + wm * 32 + mf * 16 + g;
#pragma unroll
            for (int h = 0; h < 2; h++) {
                int row = r0 + h * 8;
                if (row < Mrows) {
                    float vx = acc[mf][nf][h * 2 + 0] + bx;
                    float vy = acc[mf][nf][h * 2 + 1] + by;
                    if (MODE == 1) { vx = fmaxf(vx, 0.f); vy = fmaxf(vy, 0.f); }
                    *reinterpret_cast<float2*>(Opt + (size_t)row * FDIM + col) =
                        make_float2(vx, vy);
                }
            }
        }
    }
}

// ---------------- edge pass: seg-max of r=ReLU(P[l]-Q[c]) + BN1 stats ----------------
// 160 threads, thread t<150 owns float2 columns (2t, 2t+1). Q on the fly.
#define SEGS 32
#define ETHR 160
__global__ __launch_bounds__(ETHR)
void k_edge(const float* __restrict__ cur_coors, const float* __restrict__ W1, int nCur) {
    __shared__ float sW[3 * FDIM];
    int t = threadIdx.x;
    for (int i = t; i < 3 * FDIM; i += ETHR) {
        int r = i / FDIM, n = i - r * FDIM;
        sW[i] = W1[(size_t)(FDIM + r) * FDIM + n];
    }
    __syncthreads();

    bool act = (t < FDIM / 2);          // 150 active threads
    int c0 = 2 * t, c1 = 2 * t + 1;
    int segBase = blockIdx.x * SEGS;

    float s0 = 0.f, s1 = 0.f, sq0 = 0.f, sq1 = 0.f;

    for (int si = 0; si < SEGS; si++) {
        int c = segBase + si;
        if (c >= nCur) break;
        int e0 = g_offs[c];
        int e1 = g_offs[c + 1];
        if (e0 == e1 || !act) continue;

        float x0 = cur_coors[c * 3 + 0];
        float x1 = cur_coors[c * 3 + 1];
        float x2 = cur_coors[c * 3 + 2];
        float qx = fmaf(x2, sW[2 * FDIM + c0], fmaf(x1, sW[FDIM + c0], x0 * sW[c0]));
        float qy = fmaf(x2, sW[2 * FDIM + c1], fmaf(x1, sW[FDIM + c1], x0 * sW[c1]));

        float m0 = 0.f, m1 = 0.f;
        int l = g_sortedLast[e0];
        for (int e = e0; e < e1; e++) {
            int ln = (e + 1 < e1) ? g_sortedLast[e + 1] : 0;
            float2 p = *reinterpret_cast<const float2*>(g_P + (size_t)l * FDIM + c0);
            float r0 = fmaxf(p.x - qx, 0.f);
            float r1 = fmaxf(p.y - qy, 0.f);
            m0 = fmaxf(m0, r0); s0 += r0; sq0 += r0 * r0;
            m1 = fmaxf(m1, r1); s1 += r1; sq1 += r1 * r1;
            l = ln;
        }
        *reinterpret_cast<float2*>(g_M + (size_t)c * FDIM + c0) = make_float2(m0, m1);
    }

    if (act) {
        atomicAdd(&g_sum1[c0], s0);   atomicAdd(&g_sumsq1[c0], sq0);
        atomicAdd(&g_sum1[c1], s1);   atomicAdd(&g_sumsq1[c1], sq1);
    }
}

// ---------------- BN1 affine params from edge-pass stats ----------------
__global__ void k_bnparam(const float* __restrict__ g1, const float* __restrict__ be1, int E) {
    int n = blockIdx.x * blockDim.x + threadIdx.x;
    if (n >= FDIM) return;
    float invE = 1.f / (float)E;
    float mean = g_sum1[n] * invE;
    float var  = fmaxf(g_sumsq1[n] * invE - mean * mean, 0.f);
    float a = g1[n] * rsqrtf(var + BN_EPS);
    g_a1[n] = a;
    g_c1[n] = be1[n] - mean * a;
}

// ---------------- BN2 stats over out ----------------
__global__ __launch_bounds__(320)
void k_stats2(const float* __restrict__ out, int nCur) {
    int c = threadIdx.x;
    if (c >= FDIM) return;
    int r0 = blockIdx.x * 128;
    int r1 = r0 + 128; if (r1 > nCur) r1 = nCur;
    float s = 0.f, q = 0.f;
    for (int r = r0; r < r1; r++) {
        float v = out[(size_t)r * FDIM + c];
        s += v; q += v * v;
    }
    atomicAdd(&g_sum2[c], s);
    atomicAdd(&g_sumsq2[c], q);
}

// ---------------- final BN2 over d_out (in place, float2) ----------------
__global__ void k_bn2(const float* __restrict__ g2, const float* __restrict__ be2,
                      float* __restrict__ out, int nCur) {
    int idx = blockIdx.x * blockDim.x + threadIdx.x;      // float2 units
    int total = nCur * (FDIM / 2);
    if (idx >= total) return;
    int cp = idx % (FDIM / 2);
    int n0 = 2 * cp, n1 = n0 + 1;
    float invN = 1.f / (float)nCur;
    float mean0 = g_sum2[n0] * invN, mean1 = g_sum2[n1] * invN;
    float var0 = fmaxf(g_sumsq2[n0] * invN - mean0 * mean0, 0.f);
    float var1 = fmaxf(g_sumsq2[n1] * invN - mean1 * mean1, 0.f);
    float a0 = g2[n0] * rsqrtf(var0 + BN_EPS);
    float a1 = g2[n1] * rsqrtf(var1 + BN_EPS);
    float b0 = be2[n0] - mean0 * a0;
    float b1 = be2[n1] - mean1 * a1;
    float2* p = reinterpret_cast<float2*>(out) + idx;
    float2 v = *p;
    *p = make_float2(fmaf(a0, v.x, b0), fmaf(a1, v.y, b1));
}

// ---------------- launch ----------------
extern "C" void kernel_launch(void* const* d_in, const int* in_sizes, int n_in,
                              void* d_out, int out_size) {
    const float* last_coors    = (const float*)d_in[0];
    const float* last_features = (const float*)d_in[1];
    const float* current_coors = (const float*)d_in[2];
    const int*   cur_idx       = (const int*)d_in[3];
    const int*   last_idx      = (const int*)d_in[4];
    const float* W1            = (const float*)d_in[5];
    const float* b1            = (const float*)d_in[6];
    const float* g1            = (const float*)d_in[7];
    const float* be1           = (const float*)d_in[8];
    const float* W2            = (const float*)d_in[9];
    const float* b2            = (const float*)d_in[10];
    const float* g2            = (const float*)d_in[11];
    const float* be2           = (const float*)d_in[12];
    float* out = (float*)d_out;

    int nLast = in_sizes[0] / 3;
    int nCur  = in_sizes[2] / 3;
    int E     = in_sizes[3];
    int nb    = (nCur + 1023) / 1024;

    cudaFuncSetAttribute(k_gemm_mma<0>, cudaFuncAttributeMaxDynamicSharedMemorySize, SMEM_TOT);
    cudaFuncSetAttribute(k_gemm_mma<1>, cudaFuncAttributeMaxDynamicSharedMemorySize, SMEM_TOT);

    // 1: W images
    k_convW<<<(2 * NPAD * NPAD + 255) / 256, 256>>>(W1, W2);
    // 2: init counters/stats
    {
        int n = nCur > FDIM ? nCur : FDIM;
        k_init<<<(n + 255) / 256, 256>>>(nCur);
    }
    // 3: histogram
    k_hist<<<(E + 255) / 256, 256>>>(cur_idx, E);
    // 4: GEMM1: P = [feats|coors] @ W1 + b1 -> g_P
    {
        dim3 grid((nLast + 127) / 128, 2);
        k_gemm_mma<0><<<grid, 512, SMEM_TOT>>>(last_features, last_coors, b1, nullptr, nLast);
    }
    // 5-8: parallel counting-sort scan + scatter
    k_scanA<<<nb, 1024>>>(nCur);
    k_scanB<<<1, 32>>>(nCur, nb);
    k_scanC<<<(nCur + 255) / 256, 256>>>(nCur);
    k_scatter<<<(E + 255) / 256, 256>>>(cur_idx, last_idx, E);
    // 9: edge pass (fused Q): seg-max + BN1 stats -> g_M, g_sum1/g_sumsq1
    k_edge<<<(nCur + SEGS - 1) / SEGS, ETHR>>>(current_coors, W1, nCur);
    // 10: BN1 affine params
    k_bnparam<<<(FDIM + 127) / 128, 128>>>(g1, be1, E);
    // 11: GEMM2 (BN1 affine fused into A-fill): out = ReLU(BN1(g_M) @ W2 + b2)
    {
        dim3 grid((nCur + 127) / 128, 2);
        k_gemm_mma<1><<<grid, 512, SMEM_TOT>>>(nullptr, nullptr, b2, out, nCur);
    }
    // 12-13: BN2 stats + final affine
    k_stats2<<<(nCur + 127) / 128, 320>>>(out, nCur);
    k_bn2<<<(nCur * (FDIM / 2) + 255) / 256, 256>>>(g2, be2, out, nCur);
}